// round 3
// baseline (speedup 1.0000x reference)
#include <cuda_runtime.h>

typedef unsigned long long ull;

// ---------------- f32x2 packed math (FFMA2 — PTX-only on sm_103a) ----------
#define FMA2(d,a,b,c) asm("fma.rn.f32x2 %0, %1, %2, %3;" : "=l"(d) : "l"(a), "l"(b), "l"(c))
#define MUL2(d,a,b)   asm("mul.rn.f32x2 %0, %1, %2;"     : "=l"(d) : "l"(a), "l"(b))
#define ADD2(d,a,b)   asm("add.rn.f32x2 %0, %1, %2;"     : "=l"(d) : "l"(a), "l"(b))
#define EX2(d,s)      asm("ex2.approx.f32 %0, %1;"       : "=f"(d) : "f"(s))

__device__ __forceinline__ ull splat2(float f) {
    unsigned u = __float_as_uint(f);
    return ((ull)u << 32) | (ull)u;
}
__device__ __forceinline__ float lo2(ull v) { return __uint_as_float((unsigned)v); }
__device__ __forceinline__ float hi2(ull v) { return __uint_as_float((unsigned)(v >> 32)); }
__device__ __forceinline__ ull pack2(float lo, float hi) {
    return ((ull)__float_as_uint(hi) << 32) | (ull)__float_as_uint(lo);
}

// ---------------- problem constants ----------------------------------------
// B=2, C=256, N=4096, NUM_HEAD=4, D=8, AT_HEAD=64, BH=8
#define NTOK   4096
#define BH_CNT 8
#define NSPLIT 8                 // n-range splits
#define NSEG   (NTOK / NSPLIT)   // 512 n per attn CTA

#define LOG2E  1.4426950408889634f

// ---------------- device scratch (no allocation allowed) -------------------
// Q/V: interleaved pair layout [bh][n/2][d*2 + (n&1)]   (q pre-scaled by log2e)
// K  : [bh][n][d]
__device__ float g_Q[BH_CNT * NTOK * 8];
__device__ float g_K[BH_CNT * NTOK * 8];
__device__ float g_V[BH_CNT * NTOK * 8];
// partials: [bh][split][j in 0..8 (8 num + 1 den)][m]
__device__ float g_P[BH_CNT * NSPLIT * 9 * NTOK];

// ============================================================================
// Kernel 1: fused QKV projection as smem-tiled GEMM.
// C[96 x 8192] = W[96 x 256] @ X[256 x 8192]. 512 blocks, 16 n-cols each.
// ============================================================================
#define KCH   64                 // k per W chunk
#define K4CH  (KCH / 4)          // 16

__global__ void __launch_bounds__(256) qkv_kernel(
    const float* __restrict__ x,
    const float* __restrict__ Wq, const float* __restrict__ bq,
    const float* __restrict__ Wk, const float* __restrict__ bk,
    const float* __restrict__ Wv, const float* __restrict__ bv)
{
    __shared__ __align__(16) float4 xs4[64 * 16];     // [k4][n]  16 KB
    __shared__ __align__(16) float4 ws4[K4CH * 96];   // [k4l][r] 24 KB

    const int b   = blockIdx.x >> 8;            // 512 blocks: 256 per b
    const int n0  = (blockIdx.x & 255) * 16;
    const int tid = threadIdx.x;

    // stage x tile: x[b][c][n0..n0+15] -> xs4[c>>2][n] component c&3
    float* xs_f = (float*)xs4;
    for (int i = tid; i < 1024; i += 256) {      // 4 iters, LDG.128 over n
        int c  = i >> 2;
        int nq = i & 3;
        float4 xv = __ldg((const float4*)(x + (b * 256 + c) * NTOK + n0) + nq);
        float* dst = xs_f + (c >> 2) * 64 + (c & 3);
        dst[(nq * 4 + 0) * 4] = xv.x;
        dst[(nq * 4 + 1) * 4] = xv.y;
        dst[(nq * 4 + 2) * 4] = xv.z;
        dst[(nq * 4 + 3) * 4] = xv.w;
    }

    const int rg = tid >> 4;     // row group 0..15 (6 rows each)
    const int nl = tid & 15;     // local n

    float acc[6];
#pragma unroll
    for (int rr = 0; rr < 6; ++rr) acc[rr] = 0.0f;

    for (int kc = 0; kc < 4; ++kc) {
        __syncthreads();
        // stage W chunk: ws4[k4l][r] = W[r][kc*64 + 4*k4l .. +3]
        for (int i = tid; i < 96 * K4CH; i += 256) {   // 6 iters
            int r   = i >> 4;
            int k4l = i & 15;
            const float* base = (r < 32) ? Wq : ((r < 64) ? Wk : Wv);
            float4 w = __ldg((const float4*)(base + (r & 31) * 256 + kc * KCH) + k4l);
            ws4[k4l * 96 + r] = w;
        }
        __syncthreads();

#pragma unroll
        for (int k4l = 0; k4l < K4CH; ++k4l) {
            float4 xv = xs4[(kc * K4CH + k4l) * 16 + nl];
            const float4* wrow = &ws4[k4l * 96 + rg * 6];
#pragma unroll
            for (int rr = 0; rr < 6; ++rr) {
                float4 w = wrow[rr];
                acc[rr] += w.x * xv.x + w.y * xv.y + w.z * xv.z + w.w * xv.w;
            }
        }
    }

    // write out with bias, into attention-friendly layouts
    const int n = n0 + nl;
#pragma unroll
    for (int rr = 0; rr < 6; ++rr) {
        int r = rg * 6 + rr;
        int p = r >> 5;          // 0=q,1=k,2=v
        int h = (r >> 3) & 3;
        int d = r & 7;
        const float* bias = (p == 0) ? bq : ((p == 1) ? bk : bv);
        float val = acc[rr] + __ldg(&bias[h * 8 + d]);
        int bh = b * 4 + h;
        if (p == 0) {
            // fold log2e (for ex2-based exp) into q
            g_Q[bh * (NTOK * 8) + (n >> 1) * 16 + d * 2 + (n & 1)] = LOG2E * val;
        } else if (p == 1) {
            g_K[bh * (NTOK * 8) + n * 8 + d] = val;
        } else {
            g_V[bh * (NTOK * 8) + (n >> 1) * 16 + d * 2 + (n & 1)] = val;
        }
    }
}

// ============================================================================
// Kernel 2: fused attention core.
// Grid: x = (m-tile 0..7) | (split 0..7)<<3 ; y = bh.  512 blocks.
// CTA: 256 threads, each owns 2 m-columns, streams a 512-n slice of (q, v)
// from smem as f32x2 n-pairs. exp(S) = ex2(S*log2e) on the MUFU pipe.
// ============================================================================
__global__ void __launch_bounds__(256) attn_kernel()
{
    __shared__ __align__(16) float sq[NSEG * 8];   // 16 KB
    __shared__ __align__(16) float sv[NSEG * 8];   // 16 KB

    const int bh  = blockIdx.y;
    const int mt  = blockIdx.x & 7;
    const int sp  = blockIdx.x >> 3;
    const int tid = threadIdx.x;

    const float4* Qb = (const float4*)(g_Q + bh * (NTOK * 8) + sp * (NSEG * 8));
    const float4* Vb = (const float4*)(g_V + bh * (NTOK * 8) + sp * (NSEG * 8));
    for (int i = tid; i < NSEG * 8 / 4; i += 256) {
        ((float4*)sq)[i] = Qb[i];
        ((float4*)sv)[i] = Vb[i];
    }

    // k for this thread's 2 m-columns, splatted into f32x2
    ull k2[2][8];
#pragma unroll
    for (int j = 0; j < 2; ++j) {
        int m = mt * 512 + tid + j * 256;
        const float4* kp = (const float4*)(g_K + bh * (NTOK * 8) + m * 8);
        float4 ka = __ldg(kp), kb = __ldg(kp + 1);
        k2[j][0] = splat2(ka.x); k2[j][1] = splat2(ka.y);
        k2[j][2] = splat2(ka.z); k2[j][3] = splat2(ka.w);
        k2[j][4] = splat2(kb.x); k2[j][5] = splat2(kb.y);
        k2[j][6] = splat2(kb.z); k2[j][7] = splat2(kb.w);
    }

    ull num2[2][8], den2[2];
#pragma unroll
    for (int j = 0; j < 2; ++j) {
        den2[j] = 0ull;
#pragma unroll
        for (int d = 0; d < 8; ++d) num2[j][d] = 0ull;
    }

    __syncthreads();

#pragma unroll 2
    for (int p = 0; p < NSEG / 2; ++p) {
        // q2[d] = (q[d][2p], q[d][2p+1]) — 4x LDS.128, broadcast across CTA
        const ulonglong2* qp = (const ulonglong2*)sq + p * 4;
        ull q2[8];
        {
            ulonglong2 t0 = qp[0], t1 = qp[1], t2 = qp[2], t3 = qp[3];
            q2[0] = t0.x; q2[1] = t0.y; q2[2] = t1.x; q2[3] = t1.y;
            q2[4] = t2.x; q2[5] = t2.y; q2[6] = t3.x; q2[7] = t3.y;
        }

        ull s2[2];
#pragma unroll
        for (int j = 0; j < 2; ++j) {
            MUL2(s2[j], q2[0], k2[j][0]);
#pragma unroll
            for (int d = 1; d < 8; ++d) FMA2(s2[j], q2[d], k2[j][d], s2[j]);
        }

        ull e2[2];
#pragma unroll
        for (int j = 0; j < 2; ++j) {
            float el, eh;
            EX2(el, lo2(s2[j]));
            EX2(eh, hi2(s2[j]));
            e2[j] = pack2(el, eh);
            ADD2(den2[j], den2[j], e2[j]);
        }

        const ulonglong2* vp = (const ulonglong2*)sv + p * 4;
        ull v2[8];
        {
            ulonglong2 t0 = vp[0], t1 = vp[1], t2 = vp[2], t3 = vp[3];
            v2[0] = t0.x; v2[1] = t0.y; v2[2] = t1.x; v2[3] = t1.y;
            v2[4] = t2.x; v2[5] = t2.y; v2[6] = t3.x; v2[7] = t3.y;
        }
#pragma unroll
        for (int d = 0; d < 8; ++d)
#pragma unroll
            for (int j = 0; j < 2; ++j)
                FMA2(num2[j][d], e2[j], v2[d], num2[j][d]);
    }

    // write partials (coalesced over m within warp)
#pragma unroll
    for (int j = 0; j < 2; ++j) {
        int m = mt * 512 + tid + j * 256;
        int base = ((bh * NSPLIT + sp) * 9) * NTOK + m;
#pragma unroll
        for (int d = 0; d < 8; ++d)
            g_P[base + d * NTOK] = lo2(num2[j][d]) + hi2(num2[j][d]);
        g_P[base + 8 * NTOK] = lo2(den2[j]) + hi2(den2[j]);
    }
}

// ============================================================================
// Kernel 3: reduce splits, normalize, Wo projection, gamma, residual.
// 1 thread per (bh, m); 128-thread blocks -> 256 blocks.
// ============================================================================
__global__ void __launch_bounds__(128) out_kernel(
    const float* __restrict__ x,
    const float* __restrict__ Wo, const float* __restrict__ bo,
    const float* __restrict__ gamma,
    float* __restrict__ out)
{
    __shared__ float wo_s[512];
    __shared__ float bo_s[64];
    __shared__ float gam_s;

    const int t  = blockIdx.x * 128 + threadIdx.x;
    const int bh = t >> 12;
    const int m  = t & 4095;
    const int b  = bh >> 2;
    const int h  = bh & 3;

    for (int i = threadIdx.x; i < 512; i += 128) wo_s[i] = Wo[h * 512 + i];
    if (threadIdx.x < 64) bo_s[threadIdx.x] = bo[h * 64 + threadIdx.x];
    if (threadIdx.x == 0) gam_s = gamma[h];
    __syncthreads();

    float num[8];
#pragma unroll
    for (int d = 0; d < 8; ++d) num[d] = 0.0f;
    float den = 0.0f;

#pragma unroll
    for (int s = 0; s < NSPLIT; ++s) {
        const float* P = g_P + ((bh * NSPLIT + s) * 9) * NTOK + m;
#pragma unroll
        for (int d = 0; d < 8; ++d) num[d] += P[d * NTOK];
        den += P[8 * NTOK];
    }

    const float rden = 1.0f / den;
    float o[8];
#pragma unroll
    for (int d = 0; d < 8; ++d) o[d] = num[d] * rden;

    const float gam = gam_s;
#pragma unroll 4
    for (int e = 0; e < 64; ++e) {
        float y = bo_s[e];
#pragma unroll
        for (int d = 0; d < 8; ++d) y += wo_s[e * 8 + d] * o[d];
        int idx = b * (256 * NTOK) + (h * 64 + e) * NTOK + m;
        out[idx] = gam * y + x[idx];
    }
}

// ============================================================================
extern "C" void kernel_launch(void* const* d_in, const int* in_sizes, int n_in,
                              void* d_out, int out_size)
{
    const float* x     = (const float*)d_in[0];
    const float* Wq    = (const float*)d_in[1];
    const float* bq    = (const float*)d_in[2];
    const float* Wk    = (const float*)d_in[3];
    const float* bk    = (const float*)d_in[4];
    const float* Wv    = (const float*)d_in[5];
    const float* bv    = (const float*)d_in[6];
    const float* Wo    = (const float*)d_in[7];
    const float* bo    = (const float*)d_in[8];
    const float* gamma = (const float*)d_in[9];
    float* out = (float*)d_out;

    qkv_kernel<<<512, 256>>>(x, Wq, bq, Wk, bk, Wv, bv);
    attn_kernel<<<dim3(64, 8), 256>>>();
    out_kernel<<<256, 128>>>(x, Wo, bo, gamma, out);
}

// round 4
// speedup vs baseline: 1.1463x; 1.1463x over previous
#include <cuda_runtime.h>

typedef unsigned long long ull;

// ---------------- f32x2 packed math (FFMA2 — PTX-only on sm_103a) ----------
#define FMA2(d,a,b,c) asm("fma.rn.f32x2 %0, %1, %2, %3;" : "=l"(d) : "l"(a), "l"(b), "l"(c))
#define MUL2(d,a,b)   asm("mul.rn.f32x2 %0, %1, %2;"     : "=l"(d) : "l"(a), "l"(b))
#define ADD2(d,a,b)   asm("add.rn.f32x2 %0, %1, %2;"     : "=l"(d) : "l"(a), "l"(b))
#define EX2(d,s)      asm("ex2.approx.f32 %0, %1;"       : "=f"(d) : "f"(s))

__device__ __forceinline__ ull splat2(float f) {
    unsigned u = __float_as_uint(f);
    return ((ull)u << 32) | (ull)u;
}
__device__ __forceinline__ float lo2(ull v) { return __uint_as_float((unsigned)v); }
__device__ __forceinline__ float hi2(ull v) { return __uint_as_float((unsigned)(v >> 32)); }
__device__ __forceinline__ ull pack2(float lo, float hi) {
    return ((ull)__float_as_uint(hi) << 32) | (ull)__float_as_uint(lo);
}

// ---------------- problem constants ----------------------------------------
// B=2, C=256, N=4096, NUM_HEAD=4, D=8, AT_HEAD=64, BH=8
#define NTOK   4096
#define BH_CNT 8
#define NSPLIT 8                 // n-range splits
#define NSEG   (NTOK / NSPLIT)   // 512 n per attn CTA

#define LOG2E  1.4426950408889634f

// ---------------- device scratch (no allocation allowed) -------------------
// Q/V: interleaved pair layout [bh][n/2][d*2 + (n&1)]   (q pre-scaled by log2e)
// K  : [bh][n][d]
__device__ float g_Q[BH_CNT * NTOK * 8];
__device__ float g_K[BH_CNT * NTOK * 8];
__device__ float g_V[BH_CNT * NTOK * 8];
// partials: [bh][split][j in 0..8 (8 num + 1 den)][m]
__device__ float g_P[BH_CNT * NSPLIT * 9 * NTOK];

// ============================================================================
// Kernel 1: fused QKV projection, register-tiled GEMM.
// C[96 x 8192] = W[96 x 256] @ X[256 x 8192].
// 128 blocks; block = all 96 rows x 64 n of one b. 256 threads:
//   rg = tid>>5 (warp id) -> 12 rows, ng = tid&31 -> 2 n.
// Per scalar k: 1 LDS.64 (x) + 3 broadcast LDS.128 (W) -> 24 FFMA.
// k streamed in 4 chunks of 64 through smem.
// ============================================================================
#define WPAD 100   // W smem row stride (floats): mult of 4 (LDS.128 align), bank-spread

__global__ void __launch_bounds__(256) qkv_kernel(
    const float* __restrict__ x,
    const float* __restrict__ Wq, const float* __restrict__ bq,
    const float* __restrict__ Wk, const float* __restrict__ bk,
    const float* __restrict__ Wv, const float* __restrict__ bv)
{
    __shared__ __align__(16) float xs[64 * 64];     // [k_local][n]  16 KB
    __shared__ __align__(16) float ws[64 * WPAD];   // [k_local][r]  25.6 KB

    const int b   = blockIdx.x >> 6;            // 128 blocks: 64 per b
    const int n0  = (blockIdx.x & 63) * 64;
    const int tid = threadIdx.x;
    const int rg  = tid >> 5;                   // 0..7, constant per warp
    const int ng  = tid & 31;                   // 2 n each

    float acc[12][2];
#pragma unroll
    for (int rr = 0; rr < 12; ++rr) { acc[rr][0] = 0.0f; acc[rr][1] = 0.0f; }

    for (int kc = 0; kc < 4; ++kc) {
        __syncthreads();
        // stage x chunk: x[b][kc*64 + c][n0..n0+63]  (1024 float4)
#pragma unroll
        for (int t = 0; t < 4; ++t) {
            int idx = tid + t * 256;
            int c   = idx >> 4;
            int nq  = idx & 15;
            float4 xv = __ldg((const float4*)(x + (b * 256 + kc * 64 + c) * NTOK + n0) + nq);
            *(float4*)&xs[c * 64 + nq * 4] = xv;
        }
        // stage W chunk: ws[k][r] = W[r][kc*64 + k]  (1536 float4 source-side)
#pragma unroll
        for (int t = 0; t < 6; ++t) {
            int idx = tid + t * 256;
            int r   = idx >> 4;
            int k4  = idx & 15;
            const float* base = (r < 32) ? Wq : ((r < 64) ? Wk : Wv);
            float4 w = __ldg((const float4*)(base + (r & 31) * 256 + kc * 64) + k4);
            ws[(k4 * 4 + 0) * WPAD + r] = w.x;
            ws[(k4 * 4 + 1) * WPAD + r] = w.y;
            ws[(k4 * 4 + 2) * WPAD + r] = w.z;
            ws[(k4 * 4 + 3) * WPAD + r] = w.w;
        }
        __syncthreads();

#pragma unroll 8
        for (int k = 0; k < 64; ++k) {
            float2 xv = *(const float2*)&xs[k * 64 + ng * 2];
            const float* wr = &ws[k * WPAD + rg * 12];
            float4 w0 = *(const float4*)&wr[0];
            float4 w1 = *(const float4*)&wr[4];
            float4 w2 = *(const float4*)&wr[8];
            float w[12] = {w0.x, w0.y, w0.z, w0.w, w1.x, w1.y, w1.z, w1.w,
                           w2.x, w2.y, w2.z, w2.w};
#pragma unroll
            for (int rr = 0; rr < 12; ++rr) {
                acc[rr][0] += w[rr] * xv.x;
                acc[rr][1] += w[rr] * xv.y;
            }
        }
    }

    // write out with bias, into attention-friendly layouts
#pragma unroll
    for (int rr = 0; rr < 12; ++rr) {
        int r = rg * 12 + rr;
        int p = r >> 5;          // 0=q,1=k,2=v
        int h = (r >> 3) & 3;
        int d = r & 7;
        const float* bias = (p == 0) ? bq : ((p == 1) ? bk : bv);
        float bv_ = __ldg(&bias[h * 8 + d]);
        int bh = b * 4 + h;
#pragma unroll
        for (int c = 0; c < 2; ++c) {
            int n = n0 + ng * 2 + c;
            float val = acc[rr][c] + bv_;
            if (p == 0) {
                // fold log2e (for ex2-based exp) into q
                g_Q[bh * (NTOK * 8) + (n >> 1) * 16 + d * 2 + (n & 1)] = LOG2E * val;
            } else if (p == 1) {
                g_K[bh * (NTOK * 8) + n * 8 + d] = val;
            } else {
                g_V[bh * (NTOK * 8) + (n >> 1) * 16 + d * 2 + (n & 1)] = val;
            }
        }
    }
}

// ============================================================================
// Kernel 2: fused attention core (R2 structure: 4 m-cols/thread, 256 CTAs),
// exp via ex2 on the MUFU pipe (log2e folded into q).
// Grid: x = (m-tile 0..3) | (split 0..7)<<2 ; y = bh.
// ============================================================================
__global__ void __launch_bounds__(256, 1) attn_kernel()
{
    __shared__ __align__(16) float sq[NSEG * 8];   // 16 KB
    __shared__ __align__(16) float sv[NSEG * 8];   // 16 KB

    const int bh  = blockIdx.y;
    const int mt  = blockIdx.x & 3;
    const int sp  = blockIdx.x >> 2;
    const int tid = threadIdx.x;

    const float4* Qb = (const float4*)(g_Q + bh * (NTOK * 8) + sp * (NSEG * 8));
    const float4* Vb = (const float4*)(g_V + bh * (NTOK * 8) + sp * (NSEG * 8));
    for (int i = tid; i < NSEG * 8 / 4; i += 256) {
        ((float4*)sq)[i] = Qb[i];
        ((float4*)sv)[i] = Vb[i];
    }

    ull k2[4][8];
#pragma unroll
    for (int j = 0; j < 4; ++j) {
        int m = mt * 1024 + tid + j * 256;
        const float4* kp = (const float4*)(g_K + bh * (NTOK * 8) + m * 8);
        float4 ka = __ldg(kp), kb = __ldg(kp + 1);
        k2[j][0] = splat2(ka.x); k2[j][1] = splat2(ka.y);
        k2[j][2] = splat2(ka.z); k2[j][3] = splat2(ka.w);
        k2[j][4] = splat2(kb.x); k2[j][5] = splat2(kb.y);
        k2[j][6] = splat2(kb.z); k2[j][7] = splat2(kb.w);
    }

    ull num2[4][8], den2[4];
#pragma unroll
    for (int j = 0; j < 4; ++j) {
        den2[j] = 0ull;
#pragma unroll
        for (int d = 0; d < 8; ++d) num2[j][d] = 0ull;
    }

    __syncthreads();

#pragma unroll 2
    for (int p = 0; p < NSEG / 2; ++p) {
        const ulonglong2* qp = (const ulonglong2*)sq + p * 4;
        ull q2[8];
        {
            ulonglong2 t0 = qp[0], t1 = qp[1], t2 = qp[2], t3 = qp[3];
            q2[0] = t0.x; q2[1] = t0.y; q2[2] = t1.x; q2[3] = t1.y;
            q2[4] = t2.x; q2[5] = t2.y; q2[6] = t3.x; q2[7] = t3.y;
        }

        ull s2[4];
#pragma unroll
        for (int j = 0; j < 4; ++j) {
            MUL2(s2[j], q2[0], k2[j][0]);
#pragma unroll
            for (int d = 1; d < 8; ++d) FMA2(s2[j], q2[d], k2[j][d], s2[j]);
        }

        ull e2[4];
#pragma unroll
        for (int j = 0; j < 4; ++j) {
            float el, eh;
            EX2(el, lo2(s2[j]));
            EX2(eh, hi2(s2[j]));
            e2[j] = pack2(el, eh);
            ADD2(den2[j], den2[j], e2[j]);
        }

        const ulonglong2* vp = (const ulonglong2*)sv + p * 4;
        ull v2[8];
        {
            ulonglong2 t0 = vp[0], t1 = vp[1], t2 = vp[2], t3 = vp[3];
            v2[0] = t0.x; v2[1] = t0.y; v2[2] = t1.x; v2[3] = t1.y;
            v2[4] = t2.x; v2[5] = t2.y; v2[6] = t3.x; v2[7] = t3.y;
        }
#pragma unroll
        for (int d = 0; d < 8; ++d)
#pragma unroll
            for (int j = 0; j < 4; ++j)
                FMA2(num2[j][d], e2[j], v2[d], num2[j][d]);
    }

#pragma unroll
    for (int j = 0; j < 4; ++j) {
        int m = mt * 1024 + tid + j * 256;
        int base = ((bh * NSPLIT + sp) * 9) * NTOK + m;
#pragma unroll
        for (int d = 0; d < 8; ++d)
            g_P[base + d * NTOK] = lo2(num2[j][d]) + hi2(num2[j][d]);
        g_P[base + 8 * NTOK] = lo2(den2[j]) + hi2(den2[j]);
    }
}

// ============================================================================
// Kernel 3: reduce splits, normalize, Wo projection, gamma, residual.
// ============================================================================
__global__ void __launch_bounds__(128) out_kernel(
    const float* __restrict__ x,
    const float* __restrict__ Wo, const float* __restrict__ bo,
    const float* __restrict__ gamma,
    float* __restrict__ out)
{
    __shared__ float wo_s[512];
    __shared__ float bo_s[64];
    __shared__ float gam_s;

    const int t  = blockIdx.x * 128 + threadIdx.x;
    const int bh = t >> 12;
    const int m  = t & 4095;
    const int b  = bh >> 2;
    const int h  = bh & 3;

    for (int i = threadIdx.x; i < 512; i += 128) wo_s[i] = Wo[h * 512 + i];
    if (threadIdx.x < 64) bo_s[threadIdx.x] = bo[h * 64 + threadIdx.x];
    if (threadIdx.x == 0) gam_s = gamma[h];
    __syncthreads();

    float num[8];
#pragma unroll
    for (int d = 0; d < 8; ++d) num[d] = 0.0f;
    float den = 0.0f;

#pragma unroll
    for (int s = 0; s < NSPLIT; ++s) {
        const float* P = g_P + ((bh * NSPLIT + s) * 9) * NTOK + m;
#pragma unroll
        for (int d = 0; d < 8; ++d) num[d] += P[d * NTOK];
        den += P[8 * NTOK];
    }

    const float rden = 1.0f / den;
    float o[8];
#pragma unroll
    for (int d = 0; d < 8; ++d) o[d] = num[d] * rden;

    const float gam = gam_s;
#pragma unroll 4
    for (int e = 0; e < 64; ++e) {
        float y = bo_s[e];
#pragma unroll
        for (int d = 0; d < 8; ++d) y += wo_s[e * 8 + d] * o[d];
        int idx = b * (256 * NTOK) + (h * 64 + e) * NTOK + m;
        out[idx] = gam * y + x[idx];
    }
}

// ============================================================================
extern "C" void kernel_launch(void* const* d_in, const int* in_sizes, int n_in,
                              void* d_out, int out_size)
{
    const float* x     = (const float*)d_in[0];
    const float* Wq    = (const float*)d_in[1];
    const float* bq    = (const float*)d_in[2];
    const float* Wk    = (const float*)d_in[3];
    const float* bk    = (const float*)d_in[4];
    const float* Wv    = (const float*)d_in[5];
    const float* bv    = (const float*)d_in[6];
    const float* Wo    = (const float*)d_in[7];
    const float* bo    = (const float*)d_in[8];
    const float* gamma = (const float*)d_in[9];
    float* out = (float*)d_out;

    qkv_kernel<<<128, 256>>>(x, Wq, bq, Wk, bk, Wv, bv);
    attn_kernel<<<dim3(32, 8), 256>>>();
    out_kernel<<<256, 128>>>(x, Wo, bo, gamma, out);
}